// round 1
// baseline (speedup 1.0000x reference)
#include <cuda_runtime.h>
#include <math.h>

#define T_TOK 4096
#define DDIM  1024
#define HDIM  4096
#define NEXP  8

// ---------------- device scratch (static: no allocations allowed) ----------
__device__ int   g_counts[NEXP];
__device__ int   g_fill[NEXP];
__device__ int   g_offsets[NEXP + 1];
__device__ int   g_topi[T_TOK * 2];
__device__ float g_topw[T_TOK * 2];
__device__ int   g_token[T_TOK * 2];
__device__ float g_weight[T_TOK * 2];
__device__ float g_h[(size_t)T_TOK * 2 * HDIM];   // 134 MB gelu(h) scratch

// ---------------- init: zero output + counters -----------------------------
__global__ void k_init(float* out) {
    int i = blockIdx.x * blockDim.x + threadIdx.x;
    if (i < T_TOK * DDIM) out[i] = 0.0f;
    if (i < NEXP) { g_counts[i] = 0; g_fill[i] = 0; }
}

// ---------------- router: logits -> top2 -> renorm --------------------------
__global__ void k_router(const float* __restrict__ x, const float* __restrict__ rw) {
    __shared__ float srw[NEXP * DDIM];  // 32 KB
    for (int i = threadIdx.x; i < NEXP * DDIM; i += blockDim.x) srw[i] = rw[i];
    __syncthreads();

    int warp = threadIdx.x >> 5, lane = threadIdx.x & 31;
    int t = blockIdx.x * 8 + warp;
    if (t >= T_TOK) return;
    const float* xr = x + (size_t)t * DDIM;

    float acc[NEXP];
#pragma unroll
    for (int e = 0; e < NEXP; e++) acc[e] = 0.0f;

    for (int d = lane; d < DDIM; d += 32) {
        float xv = xr[d];
#pragma unroll
        for (int e = 0; e < NEXP; e++) acc[e] += xv * srw[e * DDIM + d];
    }
#pragma unroll
    for (int off = 16; off > 0; off >>= 1)
#pragma unroll
        for (int e = 0; e < NEXP; e++) acc[e] += __shfl_down_sync(0xffffffffu, acc[e], off);

    if (lane == 0) {
        float mx = acc[0];
#pragma unroll
        for (int e = 1; e < NEXP; e++) mx = fmaxf(mx, acc[e]);
        float p[NEXP];
#pragma unroll
        for (int e = 0; e < NEXP; e++) p[e] = expf(acc[e] - mx);
        // top-2 (ties -> lower index first, matching top_k)
        int i0 = 0;
#pragma unroll
        for (int e = 1; e < NEXP; e++) if (p[e] > p[i0]) i0 = e;
        int i1 = (i0 == 0) ? 1 : 0;
#pragma unroll
        for (int e = 0; e < NEXP; e++) if (e != i0 && p[e] > p[i1]) i1 = e;
        float w0 = p[i0], w1 = p[i1];
        float s = w0 + w1;
        w0 /= s; w1 /= s;
        g_topi[2 * t] = i0;     g_topw[2 * t] = w0;
        g_topi[2 * t + 1] = i1; g_topw[2 * t + 1] = w1;
        atomicAdd(&g_counts[i0], 1);
        atomicAdd(&g_counts[i1], 1);
    }
}

// ---------------- prefix sum over 8 counts ----------------------------------
__global__ void k_offsets() {
    if (threadIdx.x == 0 && blockIdx.x == 0) {
        int s = 0;
        for (int e = 0; e < NEXP; e++) { g_offsets[e] = s; s += g_counts[e]; }
        g_offsets[NEXP] = s;
    }
}

// ---------------- scatter tokens into compact per-expert lists --------------
__global__ void k_scatter() {
    int t = blockIdx.x * blockDim.x + threadIdx.x;
    if (t >= T_TOK) return;
#pragma unroll
    for (int k = 0; k < 2; k++) {
        int e = g_topi[2 * t + k];
        int pos = g_offsets[e] + atomicAdd(&g_fill[e], 1);
        g_token[pos] = t;
        g_weight[pos] = g_topw[2 * t + k];
    }
}

// ---------------- GEMM1: h = gelu(Xg @ w1[e]^T + b1[e]) ---------------------
// 128x128x16 tile, 256 threads, 8x8 per thread
__global__ __launch_bounds__(256, 2) void k_gemm1(
    const float* __restrict__ x, const float* __restrict__ w1,
    const float* __restrict__ b1)
{
    int e = blockIdx.z;
    int base = g_offsets[e];
    int cnt = g_offsets[e + 1] - base;
    int m0 = blockIdx.y * 128;
    if (m0 >= cnt) return;
    int n0 = blockIdx.x * 128;

    __shared__ float As[16][132];
    __shared__ float Bs[16][132];
    __shared__ int stok[128];

    int tid = threadIdx.x;
    if (tid < 128) stok[tid] = (m0 + tid < cnt) ? g_token[base + m0 + tid] : -1;
    __syncthreads();

    const float* Bbase = w1 + (size_t)e * HDIM * DDIM + (size_t)n0 * DDIM;

    float acc[8][8];
#pragma unroll
    for (int i = 0; i < 8; i++)
#pragma unroll
        for (int j = 0; j < 8; j++) acc[i][j] = 0.0f;

    int tx = tid & 15, ty = tid >> 4;

    for (int k0 = 0; k0 < DDIM; k0 += 16) {
#pragma unroll
        for (int i = 0; i < 2; i++) {
            int f = tid + i * 256;
            int m = f >> 2, kq = f & 3;
            int tok = stok[m];
            float4 v = make_float4(0.f, 0.f, 0.f, 0.f);
            if (tok >= 0) v = *(const float4*)(x + (size_t)tok * DDIM + k0 + kq * 4);
            As[kq * 4 + 0][m] = v.x; As[kq * 4 + 1][m] = v.y;
            As[kq * 4 + 2][m] = v.z; As[kq * 4 + 3][m] = v.w;
        }
#pragma unroll
        for (int i = 0; i < 2; i++) {
            int f = tid + i * 256;
            int n = f >> 2, kq = f & 3;
            float4 v = *(const float4*)(Bbase + (size_t)n * DDIM + k0 + kq * 4);
            Bs[kq * 4 + 0][n] = v.x; Bs[kq * 4 + 1][n] = v.y;
            Bs[kq * 4 + 2][n] = v.z; Bs[kq * 4 + 3][n] = v.w;
        }
        __syncthreads();
#pragma unroll
        for (int kk = 0; kk < 16; kk++) {
            float a[8], b[8];
#pragma unroll
            for (int i = 0; i < 8; i++) a[i] = As[kk][ty + 16 * i];
#pragma unroll
            for (int j = 0; j < 8; j++) b[j] = Bs[kk][tx + 16 * j];
#pragma unroll
            for (int i = 0; i < 8; i++)
#pragma unroll
                for (int j = 0; j < 8; j++) acc[i][j] += a[i] * b[j];
        }
        __syncthreads();
    }

#pragma unroll
    for (int i = 0; i < 8; i++) {
        int m = ty + 16 * i;
        if (m0 + m >= cnt) continue;
        size_t row = (size_t)(base + m0 + m);
#pragma unroll
        for (int j = 0; j < 8; j++) {
            int n = n0 + tx + 16 * j;
            float v = acc[i][j] + b1[e * HDIM + n];
            float g = 0.5f * v * (1.0f + erff(v * 0.70710678118654752f));
            g_h[row * HDIM + n] = g;
        }
    }
}

// ---------------- GEMM2: out += w * (h @ w2[e]^T + b2[e]) -------------------
__global__ __launch_bounds__(256, 2) void k_gemm2(
    const float* __restrict__ w2, const float* __restrict__ b2,
    float* __restrict__ out)
{
    int e = blockIdx.z;
    int base = g_offsets[e];
    int cnt = g_offsets[e + 1] - base;
    int m0 = blockIdx.y * 128;
    if (m0 >= cnt) return;
    int n0 = blockIdx.x * 128;

    __shared__ float As[16][132];
    __shared__ float Bs[16][132];
    __shared__ int stok[128];
    __shared__ float sw[128];

    int tid = threadIdx.x;
    if (tid < 128) {
        bool valid = (m0 + tid < cnt);
        stok[tid] = valid ? g_token[base + m0 + tid] : -1;
        sw[tid] = valid ? g_weight[base + m0 + tid] : 0.0f;
    }
    __syncthreads();

    const float* Bbase = w2 + (size_t)e * DDIM * HDIM + (size_t)n0 * HDIM;
    const float* Abase = g_h + (size_t)(base + m0) * HDIM;

    float acc[8][8];
#pragma unroll
    for (int i = 0; i < 8; i++)
#pragma unroll
        for (int j = 0; j < 8; j++) acc[i][j] = 0.0f;

    int tx = tid & 15, ty = tid >> 4;

    for (int k0 = 0; k0 < HDIM; k0 += 16) {
#pragma unroll
        for (int i = 0; i < 2; i++) {
            int f = tid + i * 256;
            int m = f >> 2, kq = f & 3;
            float4 v = make_float4(0.f, 0.f, 0.f, 0.f);
            if (m0 + m < cnt) v = *(const float4*)(Abase + (size_t)m * HDIM + k0 + kq * 4);
            As[kq * 4 + 0][m] = v.x; As[kq * 4 + 1][m] = v.y;
            As[kq * 4 + 2][m] = v.z; As[kq * 4 + 3][m] = v.w;
        }
#pragma unroll
        for (int i = 0; i < 2; i++) {
            int f = tid + i * 256;
            int n = f >> 2, kq = f & 3;
            float4 v = *(const float4*)(Bbase + (size_t)n * HDIM + k0 + kq * 4);
            Bs[kq * 4 + 0][n] = v.x; Bs[kq * 4 + 1][n] = v.y;
            Bs[kq * 4 + 2][n] = v.z; Bs[kq * 4 + 3][n] = v.w;
        }
        __syncthreads();
#pragma unroll
        for (int kk = 0; kk < 16; kk++) {
            float a[8], b[8];
#pragma unroll
            for (int i = 0; i < 8; i++) a[i] = As[kk][ty + 16 * i];
#pragma unroll
            for (int j = 0; j < 8; j++) b[j] = Bs[kk][tx + 16 * j];
#pragma unroll
            for (int i = 0; i < 8; i++)
#pragma unroll
                for (int j = 0; j < 8; j++) acc[i][j] += a[i] * b[j];
        }
        __syncthreads();
    }

#pragma unroll
    for (int i = 0; i < 8; i++) {
        int m = ty + 16 * i;
        if (m0 + m >= cnt) continue;
        int tok = stok[m];
        float w = sw[m];
#pragma unroll
        for (int j = 0; j < 8; j++) {
            int n = n0 + tx + 16 * j;
            float v = acc[i][j] + b2[e * DDIM + n];
            atomicAdd(&out[(size_t)tok * DDIM + n], w * v);
        }
    }
}

// ---------------- launch ----------------------------------------------------
extern "C" void kernel_launch(void* const* d_in, const int* in_sizes, int n_in,
                              void* d_out, int out_size) {
    const float* x   = (const float*)d_in[0];
    const float* rw  = (const float*)d_in[1];
    const float* w1  = (const float*)d_in[2];
    const float* b1  = (const float*)d_in[3];
    const float* w2  = (const float*)d_in[4];
    const float* b2  = (const float*)d_in[5];
    float* out = (float*)d_out;

    k_init<<<(T_TOK * DDIM + 255) / 256, 256>>>(out);
    k_router<<<T_TOK / 8, 256>>>(x, rw);
    k_offsets<<<1, 32>>>();
    k_scatter<<<(T_TOK + 255) / 256, 256>>>();
    k_gemm1<<<dim3(HDIM / 128, (T_TOK + 127) / 128, NEXP), 256>>>(x, w1, b1);
    k_gemm2<<<dim3(DDIM / 128, (T_TOK + 127) / 128, NEXP), 256>>>(w2, b2, out);
}

// round 3
// speedup vs baseline: 3.5034x; 3.5034x over previous
#include <cuda_runtime.h>
#include <math.h>
#include <stdint.h>

#define T_TOK 4096
#define DDIM  1024
#define HDIM  4096
#define NEXP  8

#define BM 128
#define BN 128
#define BK 32

// ---------------- device scratch ----------------
__device__ int   g_counts[NEXP];
__device__ int   g_fill[NEXP];
__device__ int   g_offsets[NEXP + 1];
__device__ int   g_topi[T_TOK * 2];
__device__ float g_topw[T_TOK * 2];
__device__ int   g_token[T_TOK * 2];
__device__ float g_weight[T_TOK * 2];
__device__ float g_h[(size_t)T_TOK * 2 * HDIM];      // 134 MB gelu(h), tf32-rounded
__device__ float g_rx[(size_t)T_TOK * DDIM];         // 16 MB  x, tf32-rounded
__device__ float g_rw1[(size_t)NEXP * HDIM * DDIM];  // 134 MB w1, tf32-rounded
__device__ float g_rw2[(size_t)NEXP * DDIM * HDIM];  // 134 MB w2, tf32-rounded

// ---------------- helpers ----------------
__device__ __forceinline__ uint32_t smem_u32(const void* p) {
    uint32_t a;
    asm("{ .reg .u64 t; cvta.to.shared.u64 t, %1; cvt.u32.u64 %0, t; }" : "=r"(a) : "l"(p));
    return a;
}
__device__ __forceinline__ float tf32r(float x) {
    uint32_t r;
    asm("cvt.rna.tf32.f32 %0, %1;" : "=r"(r) : "f"(x));
    return __uint_as_float(r);
}
__device__ __forceinline__ void cp16(uint32_t dst, const void* src, int sz) {
    asm volatile("cp.async.cg.shared.global [%0], [%1], 16, %2;"
                 :: "r"(dst), "l"(src), "r"(sz) : "memory");
}
#define CP_COMMIT() asm volatile("cp.async.commit_group;" ::: "memory")
#define CP_WAIT(N)  asm volatile("cp.async.wait_group %0;" :: "n"(N) : "memory")

__device__ __forceinline__ void mma_tf32(float* d, const uint32_t* a, const uint32_t* b) {
    asm volatile(
        "mma.sync.aligned.m16n8k8.row.col.f32.tf32.tf32.f32 "
        "{%0,%1,%2,%3}, {%4,%5,%6,%7}, {%8,%9}, {%0,%1,%2,%3};"
        : "+f"(d[0]), "+f"(d[1]), "+f"(d[2]), "+f"(d[3])
        : "r"(a[0]), "r"(a[1]), "r"(a[2]), "r"(a[3]), "r"(b[0]), "r"(b[1]));
}

// ---------------- init ----------------
__global__ void k_init(float* out) {
    int i = blockIdx.x * blockDim.x + threadIdx.x;
    if (i < T_TOK * DDIM) out[i] = 0.0f;
    if (i < NEXP) { g_counts[i] = 0; g_fill[i] = 0; }
}

// ---------------- tf32 pre-round (RN) ----------------
__global__ void k_round(const float4* __restrict__ in, float4* __restrict__ out, int n4) {
    int i = blockIdx.x * blockDim.x + threadIdx.x;
    if (i >= n4) return;
    float4 v = in[i];
    v.x = tf32r(v.x); v.y = tf32r(v.y); v.z = tf32r(v.z); v.w = tf32r(v.w);
    out[i] = v;
}

// ---------------- router ----------------
__global__ void k_router(const float* __restrict__ x, const float* __restrict__ rw) {
    __shared__ float srw[NEXP * DDIM];
    for (int i = threadIdx.x; i < NEXP * DDIM; i += blockDim.x) srw[i] = rw[i];
    __syncthreads();

    int warp = threadIdx.x >> 5, lane = threadIdx.x & 31;
    int t = blockIdx.x * 8 + warp;
    if (t >= T_TOK) return;
    const float* xr = x + (size_t)t * DDIM;

    float acc[NEXP];
#pragma unroll
    for (int e = 0; e < NEXP; e++) acc[e] = 0.0f;
    for (int d = lane; d < DDIM; d += 32) {
        float xv = xr[d];
#pragma unroll
        for (int e = 0; e < NEXP; e++) acc[e] += xv * srw[e * DDIM + d];
    }
#pragma unroll
    for (int off = 16; off > 0; off >>= 1)
#pragma unroll
        for (int e = 0; e < NEXP; e++) acc[e] += __shfl_down_sync(0xffffffffu, acc[e], off);

    if (lane == 0) {
        float mx = acc[0];
#pragma unroll
        for (int e = 1; e < NEXP; e++) mx = fmaxf(mx, acc[e]);
        float p[NEXP];
#pragma unroll
        for (int e = 0; e < NEXP; e++) p[e] = expf(acc[e] - mx);
        int i0 = 0;
#pragma unroll
        for (int e = 1; e < NEXP; e++) if (p[e] > p[i0]) i0 = e;
        int i1 = (i0 == 0) ? 1 : 0;
#pragma unroll
        for (int e = 0; e < NEXP; e++) if (e != i0 && p[e] > p[i1]) i1 = e;
        float w0 = p[i0], w1 = p[i1];
        float s = w0 + w1;
        w0 /= s; w1 /= s;
        g_topi[2 * t] = i0;     g_topw[2 * t] = w0;
        g_topi[2 * t + 1] = i1; g_topw[2 * t + 1] = w1;
        atomicAdd(&g_counts[i0], 1);
        atomicAdd(&g_counts[i1], 1);
    }
}

__global__ void k_offsets() {
    if (threadIdx.x == 0 && blockIdx.x == 0) {
        int s = 0;
        for (int e = 0; e < NEXP; e++) { g_offsets[e] = s; s += g_counts[e]; }
        g_offsets[NEXP] = s;
    }
}

__global__ void k_scatter() {
    int t = blockIdx.x * blockDim.x + threadIdx.x;
    if (t >= T_TOK) return;
#pragma unroll
    for (int k = 0; k < 2; k++) {
        int e = g_topi[2 * t + k];
        int pos = g_offsets[e] + atomicAdd(&g_fill[e], 1);
        g_token[pos] = t;
        g_weight[pos] = g_topw[2 * t + k];
    }
}

// ---------------- tf32 mma.sync grouped GEMM ----------------
// G1: D = gather(rx) @ rw1[e]^T -> gelu(.+b1) -> g_h (rounded)
// G2: D = g_h       @ rw2[e]^T -> atomicAdd(w*(.+b2)) -> out
template <int KDIM, int NTOT, bool IS_G1>
__global__ __launch_bounds__(256) void k_gemm_mma(
    const float* __restrict__ A, const float* __restrict__ W,
    const float* __restrict__ bias, float* __restrict__ outp)
{
    int e = blockIdx.z;
    int base = g_offsets[e];
    int cnt = g_offsets[e + 1] - base;
    int m0 = blockIdx.y * BM;
    if (m0 >= cnt) return;
    int n0 = blockIdx.x * BN;

    extern __shared__ float smem[];
    float* AsBase = smem;                  // 2 x [128][36]
    float* BsBase = smem + 2 * BM * 36;    // 2 x [128][36]

    __shared__ int   stok[BM];
    __shared__ float swt[BM];

    int tid = threadIdx.x;
    int wid = tid >> 5, lane = tid & 31;
    int gid = lane >> 2, tig = lane & 3;
    int wm = wid & 1, wn = wid >> 1;       // 2 x 4 warp grid; warp tile 64x32

    if (tid < BM) {
        bool v = (m0 + tid < cnt);
        stok[tid] = v ? g_token[base + m0 + tid] : -1;
        swt[tid]  = v ? g_weight[base + m0 + tid] : 0.0f;
    }
    __syncthreads();

    const float* Wbase = W + (size_t)e * NTOT * KDIM + (size_t)n0 * KDIM;
    const int C = KDIM / BK;

    auto load_chunk = [&](int c, int buf) {
        int k0 = c * BK;
        float* Ab = AsBase + buf * BM * 36;
        float* Bb = BsBase + buf * BN * 36;
#pragma unroll
        for (int i = 0; i < 4; i++) {
            int idx = tid + i * 256;
            int row = idx >> 3, q = idx & 7;
            uint32_t dst = smem_u32(&Ab[row * 36 + q * 4]);
            if (IS_G1) {
                int tok = stok[row];
                const float* src = (tok >= 0) ? (A + (size_t)tok * KDIM + k0 + q * 4) : A;
                cp16(dst, src, (tok >= 0) ? 16 : 0);
            } else {
                bool v = (m0 + row < cnt);
                const float* src = v ? (A + (size_t)(base + m0 + row) * KDIM + k0 + q * 4) : A;
                cp16(dst, src, v ? 16 : 0);
            }
        }
#pragma unroll
        for (int i = 0; i < 4; i++) {
            int idx = tid + i * 256;
            int row = idx >> 3, q = idx & 7;
            uint32_t dst = smem_u32(&Bb[row * 36 + q * 4]);
            cp16(dst, Wbase + (size_t)row * KDIM + k0 + q * 4, 16);
        }
        CP_COMMIT();
    };

    float acc[4][4][4];
#pragma unroll
    for (int mt = 0; mt < 4; mt++)
#pragma unroll
        for (int nt = 0; nt < 4; nt++)
#pragma unroll
            for (int r = 0; r < 4; r++) acc[mt][nt][r] = 0.0f;

    load_chunk(0, 0);

#pragma unroll 1
    for (int c = 0; c < C; c++) {
        if (c + 1 < C) {
            load_chunk(c + 1, (c + 1) & 1);
            CP_WAIT(1);
        } else {
            CP_WAIT(0);
        }
        __syncthreads();

        float* Ab = AsBase + (c & 1) * BM * 36;
        float* Bb = BsBase + (c & 1) * BN * 36;
#pragma unroll
        for (int ks = 0; ks < 4; ks++) {
            int k = ks * 8;
            uint32_t a[4][4], b[4][2];
#pragma unroll
            for (int mt = 0; mt < 4; mt++) {
                int r = wm * 64 + mt * 16 + gid;
                a[mt][0] = __float_as_uint(Ab[r * 36 + k + tig]);
                a[mt][1] = __float_as_uint(Ab[(r + 8) * 36 + k + tig]);
                a[mt][2] = __float_as_uint(Ab[r * 36 + k + tig + 4]);
                a[mt][3] = __float_as_uint(Ab[(r + 8) * 36 + k + tig + 4]);
            }
#pragma unroll
            for (int nt = 0; nt < 4; nt++) {
                int rB = wn * 32 + nt * 8 + gid;
                b[nt][0] = __float_as_uint(Bb[rB * 36 + k + tig]);
                b[nt][1] = __float_as_uint(Bb[rB * 36 + k + tig + 4]);
            }
#pragma unroll
            for (int mt = 0; mt < 4; mt++)
#pragma unroll
                for (int nt = 0; nt < 4; nt++)
                    mma_tf32(acc[mt][nt], a[mt], b[nt]);
        }
        __syncthreads();
    }

    // epilogue
#pragma unroll
    for (int mt = 0; mt < 4; mt++) {
#pragma unroll
        for (int nt = 0; nt < 4; nt++) {
#pragma unroll
            for (int half = 0; half < 2; half++) {
                int m = wm * 64 + mt * 16 + gid + half * 8;
                if (m0 + m >= cnt) continue;
                int ncol = n0 + wn * 32 + nt * 8 + tig * 2;
                float v0 = acc[mt][nt][half * 2 + 0] + bias[e * NTOT + ncol];
                float v1 = acc[mt][nt][half * 2 + 1] + bias[e * NTOT + ncol + 1];
                if (IS_G1) {
                    float g0 = 0.5f * v0 * (1.0f + erff(v0 * 0.70710678118654752f));
                    float g1 = 0.5f * v1 * (1.0f + erff(v1 * 0.70710678118654752f));
                    float2 st = make_float2(tf32r(g0), tf32r(g1));
                    *(float2*)(outp + (size_t)(base + m0 + m) * NTOT + ncol) = st;
                } else {
                    int tok = stok[m];
                    float w = swt[m];
                    atomicAdd(&outp[(size_t)tok * NTOT + ncol],     w * v0);
                    atomicAdd(&outp[(size_t)tok * NTOT + ncol + 1], w * v1);
                }
            }
        }
    }
}

// ---------------- launch ----------------
extern "C" void kernel_launch(void* const* d_in, const int* in_sizes, int n_in,
                              void* d_out, int out_size) {
    const float* x   = (const float*)d_in[0];
    const float* rw  = (const float*)d_in[1];
    const float* w1  = (const float*)d_in[2];
    const float* b1  = (const float*)d_in[3];
    const float* w2  = (const float*)d_in[4];
    const float* b2  = (const float*)d_in[5];
    float* out = (float*)d_out;

    const int SMEM_BYTES = 2 * (2 * BM * 36) * 4;   // 73728

    static int attr_done = 0;
    if (!attr_done) {
        cudaFuncSetAttribute(k_gemm_mma<DDIM, HDIM, true>,
                             cudaFuncAttributeMaxDynamicSharedMemorySize, SMEM_BYTES);
        cudaFuncSetAttribute(k_gemm_mma<HDIM, DDIM, false>,
                             cudaFuncAttributeMaxDynamicSharedMemorySize, SMEM_BYTES);
        attr_done = 1;
    }

    float *gh, *grx, *grw1, *grw2;
    cudaGetSymbolAddress((void**)&gh,  g_h);
    cudaGetSymbolAddress((void**)&grx, g_rx);
    cudaGetSymbolAddress((void**)&grw1, g_rw1);
    cudaGetSymbolAddress((void**)&grw2, g_rw2);

    k_init<<<(T_TOK * DDIM + 255) / 256, 256>>>(out);
    k_router<<<T_TOK / 8, 256>>>(x, rw);
    k_offsets<<<1, 32>>>();
    k_scatter<<<(T_TOK + 255) / 256, 256>>>();

    // tf32 RN pre-rounding
    k_round<<<(T_TOK * DDIM / 4 + 255) / 256, 256>>>((const float4*)x, (float4*)grx,
                                                     T_TOK * DDIM / 4);
    k_round<<<(NEXP * HDIM * DDIM / 4 + 255) / 256, 256>>>((const float4*)w1, (float4*)grw1,
                                                           NEXP * HDIM * DDIM / 4);
    k_round<<<(NEXP * DDIM * HDIM / 4 + 255) / 256, 256>>>((const float4*)w2, (float4*)grw2,
                                                           NEXP * DDIM * HDIM / 4);

    // GEMM1: rx @ rw1^T -> gelu -> g_h
    k_gemm_mma<DDIM, HDIM, true><<<dim3(HDIM / BN, T_TOK / BM, NEXP), 256, SMEM_BYTES>>>(
        grx, grw1, b1, gh);
    // GEMM2: g_h @ rw2^T -> combine -> out
    k_gemm_mma<HDIM, DDIM, false><<<dim3(DDIM / BN, T_TOK / BM, NEXP), 256, SMEM_BYTES>>>(
        gh, grw2, b2, out);
}

// round 4
// speedup vs baseline: 5.8161x; 1.6601x over previous
#include <cuda_runtime.h>
#include <cuda_fp16.h>
#include <math.h>
#include <stdint.h>

#define T_TOK 4096
#define DDIM  1024
#define HDIM  4096
#define NEXP  8

#define BM 128
#define BN 128
#define BK 64
#define ASTRIDE 72   // halves per SMEM row (64 + 8 pad => 144B, ldmatrix conflict-free)

// ---------------- device scratch ----------------
__device__ int   g_counts[NEXP];
__device__ int   g_fill[NEXP];
__device__ int   g_offsets[NEXP + 1];
__device__ int   g_topi[T_TOK * 2];
__device__ float g_topw[T_TOK * 2];
__device__ int   g_token[T_TOK * 2];
__device__ float g_weight[T_TOK * 2];
__device__ __half g_h[(size_t)T_TOK * 2 * HDIM];      // 67 MB gelu(h) fp16
__device__ __half g_xh[(size_t)T_TOK * DDIM];         // 8 MB  x fp16
__device__ __half g_w1h[(size_t)NEXP * HDIM * DDIM];  // 67 MB w1 fp16
__device__ __half g_w2h[(size_t)NEXP * DDIM * HDIM];  // 67 MB w2 fp16

// ---------------- helpers ----------------
__device__ __forceinline__ uint32_t smem_u32(const void* p) {
    uint32_t a;
    asm("{ .reg .u64 t; cvta.to.shared.u64 t, %1; cvt.u32.u64 %0, t; }" : "=r"(a) : "l"(p));
    return a;
}
__device__ __forceinline__ void cp16(uint32_t dst, const void* src, int sz) {
    asm volatile("cp.async.cg.shared.global [%0], [%1], 16, %2;"
                 :: "r"(dst), "l"(src), "r"(sz) : "memory");
}
#define CP_COMMIT() asm volatile("cp.async.commit_group;" ::: "memory")
#define CP_WAIT(N)  asm volatile("cp.async.wait_group %0;" :: "n"(N) : "memory")

__device__ __forceinline__ void ldmx4(uint32_t* r, uint32_t addr) {
    asm volatile("ldmatrix.sync.aligned.m8n8.x4.shared.b16 {%0,%1,%2,%3}, [%4];"
                 : "=r"(r[0]), "=r"(r[1]), "=r"(r[2]), "=r"(r[3]) : "r"(addr));
}
__device__ __forceinline__ void mma16(float* d, const uint32_t* a, uint32_t b0, uint32_t b1) {
    asm volatile(
        "mma.sync.aligned.m16n8k16.row.col.f32.f16.f16.f32 "
        "{%0,%1,%2,%3}, {%4,%5,%6,%7}, {%8,%9}, {%0,%1,%2,%3};"
        : "+f"(d[0]), "+f"(d[1]), "+f"(d[2]), "+f"(d[3])
        : "r"(a[0]), "r"(a[1]), "r"(a[2]), "r"(a[3]), "r"(b0), "r"(b1));
}

// ---------------- init ----------------
__global__ void k_init(float* out) {
    int i = blockIdx.x * blockDim.x + threadIdx.x;
    if (i < T_TOK * DDIM) out[i] = 0.0f;
    if (i < NEXP) { g_counts[i] = 0; g_fill[i] = 0; }
}

// ---------------- fp32 -> fp16 convert (RNE) ----------------
__global__ void k_cvt(const float4* __restrict__ in, __half2* __restrict__ out, int n4) {
    int i = blockIdx.x * blockDim.x + threadIdx.x;
    if (i >= n4) return;
    float4 v = in[i];
    out[2 * i]     = __floats2half2_rn(v.x, v.y);
    out[2 * i + 1] = __floats2half2_rn(v.z, v.w);
}

// ---------------- router ----------------
__global__ void k_router(const float* __restrict__ x, const float* __restrict__ rw) {
    __shared__ float srw[NEXP * DDIM];
    for (int i = threadIdx.x; i < NEXP * DDIM; i += blockDim.x) srw[i] = rw[i];
    __syncthreads();

    int warp = threadIdx.x >> 5, lane = threadIdx.x & 31;
    int t = blockIdx.x * 8 + warp;
    if (t >= T_TOK) return;
    const float* xr = x + (size_t)t * DDIM;

    float acc[NEXP];
#pragma unroll
    for (int e = 0; e < NEXP; e++) acc[e] = 0.0f;
    for (int d = lane; d < DDIM; d += 32) {
        float xv = xr[d];
#pragma unroll
        for (int e = 0; e < NEXP; e++) acc[e] += xv * srw[e * DDIM + d];
    }
#pragma unroll
    for (int off = 16; off > 0; off >>= 1)
#pragma unroll
        for (int e = 0; e < NEXP; e++) acc[e] += __shfl_down_sync(0xffffffffu, acc[e], off);

    if (lane == 0) {
        float mx = acc[0];
#pragma unroll
        for (int e = 1; e < NEXP; e++) mx = fmaxf(mx, acc[e]);
        float p[NEXP];
#pragma unroll
        for (int e = 0; e < NEXP; e++) p[e] = expf(acc[e] - mx);
        int i0 = 0;
#pragma unroll
        for (int e = 1; e < NEXP; e++) if (p[e] > p[i0]) i0 = e;
        int i1 = (i0 == 0) ? 1 : 0;
#pragma unroll
        for (int e = 0; e < NEXP; e++) if (e != i0 && p[e] > p[i1]) i1 = e;
        float w0 = p[i0], w1 = p[i1];
        float s = w0 + w1;
        w0 /= s; w1 /= s;
        g_topi[2 * t] = i0;     g_topw[2 * t] = w0;
        g_topi[2 * t + 1] = i1; g_topw[2 * t + 1] = w1;
        atomicAdd(&g_counts[i0], 1);
        atomicAdd(&g_counts[i1], 1);
    }
}

__global__ void k_offsets() {
    if (threadIdx.x == 0 && blockIdx.x == 0) {
        int s = 0;
        for (int e = 0; e < NEXP; e++) { g_offsets[e] = s; s += g_counts[e]; }
        g_offsets[NEXP] = s;
    }
}

__global__ void k_scatter() {
    int t = blockIdx.x * blockDim.x + threadIdx.x;
    if (t >= T_TOK) return;
#pragma unroll
    for (int k = 0; k < 2; k++) {
        int e = g_topi[2 * t + k];
        int pos = g_offsets[e] + atomicAdd(&g_fill[e], 1);
        g_token[pos] = t;
        g_weight[pos] = g_topw[2 * t + k];
    }
}

// ---------------- fp16 mma.sync grouped GEMM ----------------
// G1: D = gather(xh) @ w1h[e]^T -> gelu(.+b1) -> g_h (fp16)
// G2: D = g_h       @ w2h[e]^T -> atomicAdd(w*(.+b2)) -> out
template <int KDIM, int NTOT, bool IS_G1>
__global__ __launch_bounds__(256) void k_gemm_mma(
    const __half* __restrict__ A, const __half* __restrict__ W,
    const float* __restrict__ bias, void* __restrict__ outp)
{
    int e = blockIdx.z;
    int base = g_offsets[e];
    int cnt = g_offsets[e + 1] - base;
    int m0 = blockIdx.y * BM;
    if (m0 >= cnt) return;
    int n0 = blockIdx.x * BN;

    extern __shared__ __half smem[];
    __half* AsBase = smem;                       // 2 x [128][72]
    __half* BsBase = smem + 2 * BM * ASTRIDE;    // 2 x [128][72]

    __shared__ int   stok[BM];
    __shared__ float swt[BM];

    int tid = threadIdx.x;
    int wid = tid >> 5, lane = tid & 31;
    int wm = wid & 1, wn = wid >> 1;             // 2x4 warps; warp tile 64x32

    if (tid < BM) {
        bool v = (m0 + tid < cnt);
        stok[tid] = v ? g_token[base + m0 + tid] : -1;
        swt[tid]  = v ? g_weight[base + m0 + tid] : 0.0f;
    }
    __syncthreads();

    const __half* Wbase = W + (size_t)e * NTOT * KDIM + (size_t)n0 * KDIM;
    const int C = KDIM / BK;

    uint32_t As_u32 = smem_u32(AsBase);
    uint32_t Bs_u32 = smem_u32(BsBase);

    auto load_chunk = [&](int c, int buf) {
        int k0 = c * BK;
        uint32_t Ab = As_u32 + buf * BM * ASTRIDE * 2;
        uint32_t Bb = Bs_u32 + buf * BN * ASTRIDE * 2;
        // A: 128 rows x 64 halves = 1024 x 16B ops, 4/thread
#pragma unroll
        for (int i = 0; i < 4; i++) {
            int idx = tid + i * 256;
            int row = idx >> 3, q = idx & 7;
            uint32_t dst = Ab + (row * ASTRIDE + q * 8) * 2;
            if (IS_G1) {
                int tok = stok[row];
                const __half* src = (tok >= 0) ? (A + (size_t)tok * KDIM + k0 + q * 8) : A;
                cp16(dst, src, (tok >= 0) ? 16 : 0);
            } else {
                bool v = (m0 + row < cnt);
                const __half* src = v ? (A + (size_t)(base + m0 + row) * KDIM + k0 + q * 8) : A;
                cp16(dst, src, v ? 16 : 0);
            }
        }
#pragma unroll
        for (int i = 0; i < 4; i++) {
            int idx = tid + i * 256;
            int row = idx >> 3, q = idx & 7;
            uint32_t dst = Bb + (row * ASTRIDE + q * 8) * 2;
            cp16(dst, Wbase + (size_t)row * KDIM + k0 + q * 8, 16);
        }
        CP_COMMIT();
    };

    float acc[4][4][4];
#pragma unroll
    for (int mt = 0; mt < 4; mt++)
#pragma unroll
        for (int nt = 0; nt < 4; nt++)
#pragma unroll
            for (int r = 0; r < 4; r++) acc[mt][nt][r] = 0.0f;

    load_chunk(0, 0);

#pragma unroll 1
    for (int c = 0; c < C; c++) {
        if (c + 1 < C) {
            load_chunk(c + 1, (c + 1) & 1);
            CP_WAIT(1);
        } else {
            CP_WAIT(0);
        }
        __syncthreads();

        uint32_t Ab = As_u32 + (c & 1) * BM * ASTRIDE * 2;
        uint32_t Bb = Bs_u32 + (c & 1) * BN * ASTRIDE * 2;

#pragma unroll
        for (int ks = 0; ks < BK / 16; ks++) {
            int kh = ks * 16 + ((lane >> 4) << 3);    // col (halves) for ldmatrix
            uint32_t a[4][4], b[2][4];
            // A: rows wm*64 + mt*16 + (lane&15)
#pragma unroll
            for (int mt = 0; mt < 4; mt++) {
                int r = wm * 64 + mt * 16 + (lane & 15);
                ldmx4(a[mt], Ab + (r * ASTRIDE + kh) * 2);
            }
            // B: rows wn*32 + np*16 + (lane&15)  (np covers nt pair 2np,2np+1)
#pragma unroll
            for (int np = 0; np < 2; np++) {
                int r = wn * 32 + np * 16 + (lane & 15);
                ldmx4(b[np], Bb + (r * ASTRIDE + kh) * 2);
            }
            // b[np] regs: {b0(nt=2np), b0(nt=2np+1), b1(nt=2np), b1(nt=2np+1)}
#pragma unroll
            for (int mt = 0; mt < 4; mt++) {
#pragma unroll
                for (int np = 0; np < 2; np++) {
                    mma16(acc[mt][2 * np + 0], a[mt], b[np][0], b[np][2]);
                    mma16(acc[mt][2 * np + 1], a[mt], b[np][1], b[np][3]);
                }
            }
        }
        __syncthreads();
    }

    // epilogue: c0,c1 -> row lane/4, cols (lane&3)*2,+1 ; c2,c3 -> row+8
#pragma unroll
    for (int mt = 0; mt < 4; mt++) {
#pragma unroll
        for (int nt = 0; nt < 4; nt++) {
#pragma unroll
            for (int half = 0; half < 2; half++) {
                int m = wm * 64 + mt * 16 + (lane >> 2) + half * 8;
                if (m0 + m >= cnt) continue;
                int ncol = n0 + wn * 32 + nt * 8 + (lane & 3) * 2;
                float v0 = acc[mt][nt][half * 2 + 0] + bias[e * NTOT + ncol];
                float v1 = acc[mt][nt][half * 2 + 1] + bias[e * NTOT + ncol + 1];
                if (IS_G1) {
                    float g0 = 0.5f * v0 * (1.0f + erff(v0 * 0.70710678118654752f));
                    float g1 = 0.5f * v1 * (1.0f + erff(v1 * 0.70710678118654752f));
                    __half2* dst = (__half2*)((__half*)outp +
                                   (size_t)(base + m0 + m) * NTOT + ncol);
                    *dst = __floats2half2_rn(g0, g1);
                } else {
                    int tok = stok[m];
                    float w = swt[m];
                    float* o = (float*)outp + (size_t)tok * NTOT + ncol;
                    atomicAdd(o,     w * v0);
                    atomicAdd(o + 1, w * v1);
                }
            }
        }
    }
}

// ---------------- launch ----------------
extern "C" void kernel_launch(void* const* d_in, const int* in_sizes, int n_in,
                              void* d_out, int out_size) {
    const float* x   = (const float*)d_in[0];
    const float* rw  = (const float*)d_in[1];
    const float* w1  = (const float*)d_in[2];
    const float* b1  = (const float*)d_in[3];
    const float* w2  = (const float*)d_in[4];
    const float* b2  = (const float*)d_in[5];
    float* out = (float*)d_out;

    const int SMEM_BYTES = 2 * (2 * BM * ASTRIDE) * 2;   // 73728

    static int attr_done = 0;
    if (!attr_done) {
        cudaFuncSetAttribute(k_gemm_mma<DDIM, HDIM, true>,
                             cudaFuncAttributeMaxDynamicSharedMemorySize, SMEM_BYTES);
        cudaFuncSetAttribute(k_gemm_mma<HDIM, DDIM, false>,
                             cudaFuncAttributeMaxDynamicSharedMemorySize, SMEM_BYTES);
        attr_done = 1;
    }

    __half *gh, *gxh, *gw1h, *gw2h;
    cudaGetSymbolAddress((void**)&gh,   g_h);
    cudaGetSymbolAddress((void**)&gxh,  g_xh);
    cudaGetSymbolAddress((void**)&gw1h, g_w1h);
    cudaGetSymbolAddress((void**)&gw2h, g_w2h);

    k_init<<<(T_TOK * DDIM + 255) / 256, 256>>>(out);
    k_router<<<T_TOK / 8, 256>>>(x, rw);
    k_offsets<<<1, 32>>>();
    k_scatter<<<(T_TOK + 255) / 256, 256>>>();

    // fp32 -> fp16 conversions
    k_cvt<<<(T_TOK * DDIM / 4 + 255) / 256, 256>>>((const float4*)x, (__half2*)gxh,
                                                   T_TOK * DDIM / 4);
    k_cvt<<<(NEXP * HDIM * DDIM / 4 + 255) / 256, 256>>>((const float4*)w1, (__half2*)gw1h,
                                                         NEXP * HDIM * DDIM / 4);
    k_cvt<<<(NEXP * DDIM * HDIM / 4 + 255) / 256, 256>>>((const float4*)w2, (__half2*)gw2h,
                                                         NEXP * DDIM * HDIM / 4);

    // GEMM1: xh @ w1h^T -> gelu -> g_h (fp16)
    k_gemm_mma<DDIM, HDIM, true><<<dim3(HDIM / BN, T_TOK / BM, NEXP), 256, SMEM_BYTES>>>(
        gxh, gw1h, b1, gh);
    // GEMM2: g_h @ w2h^T -> combine -> out
    k_gemm_mma<HDIM, DDIM, false><<<dim3(DDIM / BN, T_TOK / BM, NEXP), 256, SMEM_BYTES>>>(
        gh, gw2h, b2, out);
}